// round 3
// baseline (speedup 1.0000x reference)
#include <cuda_runtime.h>
#include <cuda_bf16.h>
#include <math.h>

// Problem constants
#define B_  2
#define L_  2048
#define D_  256
#define H_  8
#define h_  32
#define C_  128           // chunk size
#define NC_ (L_ / C_)     // 16 chunks per (b,h)
#define BH_ (B_ * H_)     // 16
#define NPOS_ (BH_ * L_)  // 32768
#define EPS_ 1e-5f

// -------- scratch (device globals, no allocation) --------
__device__ float g_Q[NPOS_ * h_];      // [B,H,L,h]
__device__ float g_K[NPOS_ * h_];
__device__ float g_V[NPOS_ * h_];
__device__ float g_sim[NPOS_];
__device__ float g_gate[NPOS_];
__device__ float g_Sdelta[BH_ * NC_ * h_ * h_];
__device__ float g_Sprefix[BH_ * NC_ * h_ * h_];
__device__ float g_gsum[BH_ * NC_];
__device__ float g_mloc[BH_ * NC_];
__device__ float g_sloc[BH_ * NC_];
__device__ float g_gpre[BH_ * NC_];
__device__ float g_mpre[BH_ * NC_];
__device__ float g_spre[BH_ * NC_];
__device__ float g_ctxt[B_ * L_ * D_];  // [B,L,D]

typedef unsigned long long ull;

// -------- helpers --------
__device__ __forceinline__ float warpSum(float v) {
#pragma unroll
    for (int o = 16; o > 0; o >>= 1) v += __shfl_xor_sync(0xffffffffu, v, o);
    return v;
}
__device__ __forceinline__ float warpMax(float v) {
#pragma unroll
    for (int o = 16; o > 0; o >>= 1) v = fmaxf(v, __shfl_xor_sync(0xffffffffu, v, o));
    return v;
}
__device__ __forceinline__ ull pack2(float a, float b) {
    return (ull)__float_as_uint(a) | ((ull)__float_as_uint(b) << 32);
}
__device__ __forceinline__ float lo32(ull p) { return __uint_as_float((unsigned)p); }
__device__ __forceinline__ float hi32(ull p) { return __uint_as_float((unsigned)(p >> 32)); }
#define FFMA2(d, a, b) asm("fma.rn.f32x2 %0, %1, %2, %0;" : "+l"(d) : "l"(a), "l"(b))

// =====================================================================
// GEMM with packed f32x2 FMA.
// Out[n, o] = sum_i X[n,i]*W[o,i] + bias[o]
// Block tile 128x128, 256 threads, 8x8 per thread, K-slab 16,
// register double-buffered global->smem, X duplicated in smem for
// zero-cost (x,x) packed operands.
// mode 0: global col space is [q|k|v] (N=768), scatter to [B,H,L,h].
// mode 1: plain row-major (N=256).
// =====================================================================
#define BM_ 128
#define BN_ 128
#define KS_ 16
#define XS_PITCH (2 * BM_ + 8)   // 264 floats, 16B-aligned rows
#define WS_PITCH (BN_ + 4)       // 132 floats, 16B-aligned rows

__global__ __launch_bounds__(256, 2)
void gemm_f32x2_kernel(const float* __restrict__ X,
                       const float* __restrict__ w0,
                       const float* __restrict__ w1,
                       const float* __restrict__ w2,
                       const float* __restrict__ b0,
                       const float* __restrict__ b1,
                       const float* __restrict__ b2,
                       float* __restrict__ OutQ,
                       float* __restrict__ OutK,
                       float* __restrict__ OutV,
                       int mode) {
    __shared__ float xs[KS_][XS_PITCH];
    __shared__ float ws[KS_][WS_PITCH];

    const int tid = threadIdx.x;
    const int tx = tid & 15;
    const int ty = tid >> 4;
    const int m0 = ty * 8;
    const int n0 = tx * 8;
    const int rowBase = blockIdx.x * BM_;
    const int gc0 = blockIdx.y * BN_;          // global col base (0..767 or 0..255)
    const int matIdx = gc0 >> 8;               // which weight matrix
    const int colLoc = gc0 & 255;              // col base within that matrix

    const float* W = (matIdx == 0) ? w0 : (matIdx == 1) ? w1 : w2;
    const float* Bv = (matIdx == 0) ? b0 : (matIdx == 1) ? b1 : b2;
    float* Out = (matIdx == 0) ? OutQ : (matIdx == 1) ? OutK : OutV;

    // f4 indices this thread loads per slab (512 float4 per slab each for X, W)
    const int f4a = tid * 2;
    const int f4b = tid * 2 + 1;
    const int rowA = f4a >> 2, kqA = (f4a & 3) * 4;
    const int rowB = f4b >> 2, kqB = (f4b & 3) * 4;

    ull acc[8][4];
#pragma unroll
    for (int i = 0; i < 8; i++)
#pragma unroll
        for (int j = 0; j < 4; j++) acc[i][j] = 0ull;

    float4 xr0, xr1, wr0, wr1;

    // preload slab 0
    {
        const float* Xb = X + (size_t)(rowBase) * D_;
        const float* Wb = W + (size_t)(colLoc) * D_;
        xr0 = *(const float4*)(Xb + (size_t)rowA * D_ + kqA);
        xr1 = *(const float4*)(Xb + (size_t)rowB * D_ + kqB);
        wr0 = *(const float4*)(Wb + (size_t)rowA * D_ + kqA);
        wr1 = *(const float4*)(Wb + (size_t)rowB * D_ + kqB);
    }

    const int NS = D_ / KS_;  // 16 slabs
    for (int s = 0; s < NS; s++) {
        // store staged regs to smem (X duplicated + transposed, W transposed)
        *(ull*)&xs[kqA + 0][2 * rowA] = pack2(xr0.x, xr0.x);
        *(ull*)&xs[kqA + 1][2 * rowA] = pack2(xr0.y, xr0.y);
        *(ull*)&xs[kqA + 2][2 * rowA] = pack2(xr0.z, xr0.z);
        *(ull*)&xs[kqA + 3][2 * rowA] = pack2(xr0.w, xr0.w);
        *(ull*)&xs[kqB + 0][2 * rowB] = pack2(xr1.x, xr1.x);
        *(ull*)&xs[kqB + 1][2 * rowB] = pack2(xr1.y, xr1.y);
        *(ull*)&xs[kqB + 2][2 * rowB] = pack2(xr1.z, xr1.z);
        *(ull*)&xs[kqB + 3][2 * rowB] = pack2(xr1.w, xr1.w);
        ws[kqA + 0][rowA] = wr0.x;
        ws[kqA + 1][rowA] = wr0.y;
        ws[kqA + 2][rowA] = wr0.z;
        ws[kqA + 3][rowA] = wr0.w;
        ws[kqB + 0][rowB] = wr1.x;
        ws[kqB + 1][rowB] = wr1.y;
        ws[kqB + 2][rowB] = wr1.z;
        ws[kqB + 3][rowB] = wr1.w;
        __syncthreads();

        // prefetch next slab
        if (s + 1 < NS) {
            const int k0 = (s + 1) * KS_;
            const float* Xb = X + (size_t)(rowBase) * D_ + k0;
            const float* Wb = W + (size_t)(colLoc) * D_ + k0;
            xr0 = *(const float4*)(Xb + (size_t)rowA * D_ + kqA);
            xr1 = *(const float4*)(Xb + (size_t)rowB * D_ + kqB);
            wr0 = *(const float4*)(Wb + (size_t)rowA * D_ + kqA);
            wr1 = *(const float4*)(Wb + (size_t)rowB * D_ + kqB);
        }

        // compute
#pragma unroll
        for (int kk = 0; kk < KS_; kk++) {
            const ulonglong2* xrow = (const ulonglong2*)(&xs[kk][2 * m0]);
            ulonglong2 a0 = xrow[0];
            ulonglong2 a1 = xrow[1];
            ulonglong2 a2 = xrow[2];
            ulonglong2 a3 = xrow[3];
            const ulonglong2* wrow = (const ulonglong2*)(&ws[kk][n0]);
            ulonglong2 bb0 = wrow[0];
            ulonglong2 bb1 = wrow[1];
            ull xp[8] = {a0.x, a0.y, a1.x, a1.y, a2.x, a2.y, a3.x, a3.y};
            ull wp[4] = {bb0.x, bb0.y, bb1.x, bb1.y};
#pragma unroll
            for (int i = 0; i < 8; i++) {
#pragma unroll
                for (int j = 0; j < 4; j++) FFMA2(acc[i][j], xp[i], wp[j]);
            }
        }
        __syncthreads();
    }

    // epilogue
    float bias[8];
#pragma unroll
    for (int j = 0; j < 8; j++) bias[j] = Bv[colLoc + n0 + j];

    if (mode == 0) {
        const int gcol = gc0 + n0;          // within [0,768)
        const int head = (gcol >> 5) & 7;
        const int e = gcol & 31;            // 8-aligned, run of 8 stays in head
#pragma unroll
        for (int i = 0; i < 8; i++) {
            const int row = rowBase + m0 + i;
            const int b = row >> 11;
            const int l = row & (L_ - 1);
            float4 v0, v1;
            v0.x = lo32(acc[i][0]) + bias[0];
            v0.y = hi32(acc[i][0]) + bias[1];
            v0.z = lo32(acc[i][1]) + bias[2];
            v0.w = hi32(acc[i][1]) + bias[3];
            v1.x = lo32(acc[i][2]) + bias[4];
            v1.y = hi32(acc[i][2]) + bias[5];
            v1.z = lo32(acc[i][3]) + bias[6];
            v1.w = hi32(acc[i][3]) + bias[7];
            size_t ob = ((size_t)((b * H_ + head) * L_ + l)) * h_ + e;
            *(float4*)(Out + ob) = v0;
            *(float4*)(Out + ob + 4) = v1;
        }
    } else {
#pragma unroll
        for (int i = 0; i < 8; i++) {
            const int row = rowBase + m0 + i;
            float4 v0, v1;
            v0.x = lo32(acc[i][0]) + bias[0];
            v0.y = hi32(acc[i][0]) + bias[1];
            v0.z = lo32(acc[i][1]) + bias[2];
            v0.w = hi32(acc[i][1]) + bias[3];
            v1.x = lo32(acc[i][2]) + bias[4];
            v1.y = hi32(acc[i][2]) + bias[5];
            v1.z = lo32(acc[i][3]) + bias[6];
            v1.w = hi32(acc[i][3]) + bias[7];
            size_t ob = (size_t)row * D_ + gc0 + n0;
            *(float4*)(OutQ + ob) = v0;
            *(float4*)(OutQ + ob + 4) = v1;
        }
    }
}

// =====================================================================
// K2 (fused): per-position sim/normalize/gate + per-chunk partials.
// grid = BH*NC = 256 blocks, 256 threads (8 warps).
// =====================================================================
__global__ void chunk_fused_kernel(const float* __restrict__ kv_scale,
                                   const float* __restrict__ qk_scale,
                                   const float* __restrict__ wg_w,
                                   const float* __restrict__ wg_b) {
    __shared__ float ks[C_][33];
    __shared__ float vs[C_][33];
    __shared__ float gsh[C_];
    __shared__ float simsh[C_];
    __shared__ float msh[h_ * 33];

    int c = blockIdx.x & (NC_ - 1);
    int bh = blockIdx.x >> 4;
    int head = bh & (H_ - 1);
    int base = bh * L_ + c * C_;
    int lane = threadIdx.x & 31;
    int w = threadIdx.x >> 5;

    // stage gate matrix M = wg_w ∘ kv_scale[head] into padded smem
    for (int i = threadIdx.x; i < h_ * h_; i += 256)
        msh[(i >> 5) * 33 + (i & 31)] =
            wg_w[i] * kv_scale[(size_t)head * (h_ * h_) + i];
    __syncthreads();

    // lane d holds row d of M in registers
    float Mreg[32];
#pragma unroll
    for (int e = 0; e < 32; e++) Mreg[e] = msh[lane * 33 + e];

    float qksc = qk_scale[head];
    float gb = wg_b[0];

    // ---- pointwise stage: 16 positions per warp ----
#pragma unroll 4
    for (int j = 0; j < 16; j++) {
        int l = w * 16 + j;
        size_t gidx = (size_t)(base + l) * h_ + lane;
        float q = g_Q[gidx];
        float k = g_K[gidx];
        float v = g_V[gidx];

        float sim = warpSum(q * k) * qksc;
        float kn = sqrtf(warpSum(k * k));
        k = k / fmaxf(kn, 1e-12f);
        float vn = sqrtf(warpSum(v * v));
        v = v / fmaxf(vn, 1e-12f);

        float inner = 0.f;
#pragma unroll
        for (int e = 0; e < 32; e++)
            inner = fmaf(Mreg[e], __shfl_sync(0xffffffffu, k, e), inner);
        float logit = warpSum(v * inner) + gb;
        float r = fmaxf(logit, 0.f);
        float g = r * r + EPS_;

        ks[l][lane] = k;
        vs[l][lane] = v;
        g_K[gidx] = k;
        g_V[gidx] = v;
        if (lane == 0) {
            gsh[l] = g;
            simsh[l] = sim;
            g_gate[base + l] = g;
            g_sim[base + l] = sim;
        }
    }
    __syncthreads();

    // ---- Sdelta[d][e] = sum_i g_i * v[i][d] * k[i][e]; warp w: e=lane, d=w+8j
    float acc[4] = {0.f, 0.f, 0.f, 0.f};
    for (int i = 0; i < C_; i++) {
        float gk = gsh[i] * ks[i][lane];
#pragma unroll
        for (int j = 0; j < 4; j++) acc[j] += vs[i][w + 8 * j] * gk;
    }
    size_t sbase = (size_t)(bh * NC_ + c) * (h_ * h_);
#pragma unroll
    for (int j = 0; j < 4; j++) {
        int d = w + 8 * j;
        float sc = kv_scale[(size_t)head * (h_ * h_) + d * 32 + lane];
        g_Sdelta[sbase + d * 32 + lane] = acc[j] * sc;
    }

    // ---- scalar reductions (warp 0) ----
    if (threadIdx.x < 32) {
        float lm = -INFINITY, lg = 0.f;
#pragma unroll
        for (int j = 0; j < 4; j++) {
            lm = fmaxf(lm, simsh[lane + 32 * j]);
            lg += gsh[lane + 32 * j];
        }
        float mloc = warpMax(lm);
        float ls = 0.f;
#pragma unroll
        for (int j = 0; j < 4; j++) ls += expf(simsh[lane + 32 * j] - mloc);
        float sloc = warpSum(ls);
        float gsum = warpSum(lg);
        if (lane == 0) {
            int id = bh * NC_ + c;
            g_mloc[id] = mloc;
            g_sloc[id] = sloc;
            g_gsum[id] = gsum;
        }
    }
}

// =====================================================================
// K4: sequential exclusive scan over chunks. grid = BH = 16 blocks.
// =====================================================================
__global__ void chunk_scan_kernel() {
    int bh = blockIdx.x;
    int t = threadIdx.x;  // 256
    float acc[4] = {0.f, 0.f, 0.f, 0.f};
    for (int c = 0; c < NC_; c++) {
        size_t idx = (size_t)(bh * NC_ + c) * (h_ * h_);
#pragma unroll
        for (int j = 0; j < 4; j++) {
            g_Sprefix[idx + t + 256 * j] = acc[j];
            acc[j] += g_Sdelta[idx + t + 256 * j];
        }
    }
    if (t == 0) {
        float m = -INFINITY, s = 0.f, g = 0.f;
        for (int c = 0; c < NC_; c++) {
            int id = bh * NC_ + c;
            g_mpre[id] = m;
            g_spre[id] = s;
            g_gpre[id] = g;
            float mc = g_mloc[id], sc = g_sloc[id];
            float mn = fmaxf(m, mc);
            s = s * expf(m - mn) + sc * expf(mc - mn);
            m = mn;
            g += g_gsum[id];
        }
    }
}

// =====================================================================
// K5: chunk output. grid = BH*NC = 256 blocks, 256 threads, dyn smem.
// =====================================================================
__global__ void chunk_output_kernel() {
    extern __shared__ float sm5[];
    float* qs = sm5;                   // 128*33
    float* ks = qs + C_ * 33;          // 128*33
    float* vs = ks + C_ * 33;          // 128*33
    float* S0 = vs + C_ * 33;          // 32*33
    float* gsh = S0 + 32 * 33;         // 128
    float* simsh = gsh + C_;           // 128
    float* gcum = simsh + C_;          // 128
    float* msm = gcum + C_;            // 128
    float* ssm = msm + C_;             // 128

    int c = blockIdx.x & (NC_ - 1);
    int bh = blockIdx.x >> 4;
    int head = bh & (H_ - 1);
    int b = bh >> 3;
    int base = bh * L_ + c * C_;
    int t = threadIdx.x;

    for (int i = t; i < C_ * h_; i += 256) {
        int l = i >> 5, d = i & 31;
        qs[l * 33 + d] = g_Q[(size_t)(base + l) * h_ + d];
        ks[l * 33 + d] = g_K[(size_t)(base + l) * h_ + d];
        vs[l * 33 + d] = g_V[(size_t)(base + l) * h_ + d];
    }
    size_t sbase = (size_t)(bh * NC_ + c) * (h_ * h_);
    for (int i = t; i < h_ * h_; i += 256) {
        int d = i >> 5, e = i & 31;
        S0[d * 33 + e] = g_Sprefix[sbase + i];
    }
    for (int i = t; i < C_; i += 256) {
        float gv = g_gate[base + i];
        float sv = g_sim[base + i];
        gsh[i] = gv;
        simsh[i] = sv;
        gcum[i] = gv;
        msm[i] = sv;
        ssm[i] = 1.f;
    }
    __syncthreads();

    // Hillis-Steele inclusive scans over 128 elements
    for (int off = 1; off < C_; off <<= 1) {
        float ga = 0.f, m2 = 0.f, s2 = 0.f;
        bool rd = (t < C_) && (t >= off);
        if (rd) {
            ga = gcum[t - off];
            m2 = msm[t - off];
            s2 = ssm[t - off];
        }
        __syncthreads();
        if (rd) {
            gcum[t] += ga;
            float m1 = msm[t], s1 = ssm[t];
            float mn = fmaxf(m1, m2);
            ssm[t] = s1 * expf(m1 - mn) + s2 * expf(m2 - mn);
            msm[t] = mn;
        }
        __syncthreads();
    }

    int id = bh * NC_ + c;
    float m0 = g_mpre[id], s0 = g_spre[id], g0 = g_gpre[id];

    int l = t >> 1;
    int half = t & 1;
    int eb = half * 16;

    float acc[16];
#pragma unroll
    for (int j = 0; j < 16; j++) acc[j] = 0.f;

    // Part A: q_l @ S0
#pragma unroll 8
    for (int d = 0; d < 32; d++) {
        float qv = qs[l * 33 + d];
#pragma unroll
        for (int j = 0; j < 16; j++) acc[j] += qv * S0[d * 33 + eb + j];
    }

    // Part B: causal intra-chunk
    unsigned pmask = 3u << (t & 30);
    for (int i = 0; i <= l; i++) {
        float p = 0.f;
#pragma unroll
        for (int dd = 0; dd < 16; dd++)
            p += qs[l * 33 + eb + dd] * vs[i * 33 + eb + dd];
        p += __shfl_xor_sync(pmask, p, 1);
        p *= gsh[i];
#pragma unroll
        for (int j = 0; j < 16; j++) acc[j] += p * ks[i * 33 + eb + j];
    }

    // final scaling
    float ml = msm[l], sl = ssm[l];
    float mn = fmaxf(m0, ml);
    float sfull = s0 * expf(m0 - mn) + sl * expf(ml - mn);
    float w = expf(simsh[l] - mn) / (sfull + EPS_);
    float silu = w / (1.f + expf(-w));
    float gc = gcum[l] + g0;
    float factor = (1.f + silu) / (gc + EPS_);

    int lg = c * C_ + l;
    size_t obase = ((size_t)b * L_ + lg) * D_ + head * h_ + eb;
#pragma unroll
    for (int j = 0; j < 16; j++) g_ctxt[obase + j] = acc[j] * factor;
}

// =====================================================================
// launch
// =====================================================================
extern "C" void kernel_launch(void* const* d_in, const int* in_sizes, int n_in,
                              void* d_out, int out_size) {
    const float* x = (const float*)d_in[0];
    const float* wq_w = (const float*)d_in[1];
    const float* wq_b = (const float*)d_in[2];
    const float* wk_w = (const float*)d_in[3];
    const float* wk_b = (const float*)d_in[4];
    const float* wv_w = (const float*)d_in[5];
    const float* wv_b = (const float*)d_in[6];
    const float* wo_w = (const float*)d_in[7];
    const float* wo_b = (const float*)d_in[8];
    const float* wg_w = (const float*)d_in[9];
    const float* wg_b = (const float*)d_in[10];
    const float* kv_scale = (const float*)d_in[11];
    const float* qk_scale = (const float*)d_in[12];
    float* out = (float*)d_out;

    float* Qp; cudaGetSymbolAddress((void**)&Qp, g_Q);
    float* Kp; cudaGetSymbolAddress((void**)&Kp, g_K);
    float* Vp; cudaGetSymbolAddress((void**)&Vp, g_V);
    float* Cp; cudaGetSymbolAddress((void**)&Cp, g_ctxt);

    // fused QKV projection: N = 768 -> 6 col-blocks
    dim3 gqkv(B_ * L_ / BM_, 3 * D_ / BN_);
    gemm_f32x2_kernel<<<gqkv, 256>>>(x, wq_w, wk_w, wv_w, wq_b, wk_b, wv_b,
                                     Qp, Kp, Vp, 0);

    chunk_fused_kernel<<<BH_ * NC_, 256>>>(kv_scale, qk_scale, wg_w, wg_b);
    chunk_scan_kernel<<<BH_, 256>>>();

    const int smem5 = (3 * C_ * 33 + 32 * 33 + 5 * C_) * (int)sizeof(float);
    cudaFuncSetAttribute(chunk_output_kernel,
                         cudaFuncAttributeMaxDynamicSharedMemorySize, smem5);
    chunk_output_kernel<<<BH_ * NC_, 256, smem5>>>();

    // output projection: N = 256 -> 2 col-blocks
    dim3 gout(B_ * L_ / BM_, D_ / BN_);
    gemm_f32x2_kernel<<<gout, 256>>>(Cp, wo_w, wo_w, wo_w, wo_b, wo_b, wo_b,
                                     out, out, out, 1);
}

// round 6
// speedup vs baseline: 1.2012x; 1.2012x over previous
#include <cuda_runtime.h>
#include <cuda_bf16.h>
#include <math.h>

// Problem constants
#define B_  2
#define L_  2048
#define D_  256
#define H_  8
#define h_  32
#define C_  64            // chunk size
#define NC_ (L_ / C_)     // 32 chunks per (b,h)
#define BH_ (B_ * H_)     // 16
#define NPOS_ (BH_ * L_)  // 32768
#define EPS_ 1e-5f
#define P36 36            // float4-friendly smem pitch

// -------- scratch (device globals, no allocation) --------
__device__ float g_Q[NPOS_ * h_];      // [B,H,L,h]
__device__ float g_K[NPOS_ * h_];
__device__ float g_V[NPOS_ * h_];
__device__ float g_sim[NPOS_];
__device__ float g_gate[NPOS_];
__device__ float g_Sdelta[BH_ * NC_ * h_ * h_];
__device__ float g_Sprefix[BH_ * NC_ * h_ * h_];
__device__ float g_gsum[BH_ * NC_];
__device__ float g_mloc[BH_ * NC_];
__device__ float g_sloc[BH_ * NC_];
__device__ float g_gpre[BH_ * NC_];
__device__ float g_mpre[BH_ * NC_];
__device__ float g_spre[BH_ * NC_];
__device__ float g_ctxt[B_ * L_ * D_];  // [B,L,D]

// -------- helpers --------
__device__ __forceinline__ float warpSum(float v) {
#pragma unroll
    for (int o = 16; o > 0; o >>= 1) v += __shfl_xor_sync(0xffffffffu, v, o);
    return v;
}
__device__ __forceinline__ float warpMax(float v) {
#pragma unroll
    for (int o = 16; o > 0; o >>= 1) v = fmaxf(v, __shfl_xor_sync(0xffffffffu, v, o));
    return v;
}

// =====================================================================
// GEMM (R2 version):  Out[n,o] = sum_i X[n,i]*W[o,i] + bias[o]
// mode 0: scatter to [B,H,L,h] layout. mode 1: row-major.
// Tile 64x64, K-step 32, 256 threads, 4x4/thread.
// =====================================================================
__global__ void gemm_bias_kernel(const float* __restrict__ X,
                                 const float* __restrict__ W,
                                 const float* __restrict__ bias,
                                 float* __restrict__ Out, int mode) {
    __shared__ float xs[64][33];
    __shared__ float ws[64][33];
    const int tx = threadIdx.x & 15;
    const int ty = threadIdx.x >> 4;
    const int rowBase = blockIdx.x * 64;
    const int colBase = blockIdx.y * 64;

    float acc[4][4];
#pragma unroll
    for (int i = 0; i < 4; i++)
#pragma unroll
        for (int j = 0; j < 4; j++) acc[i][j] = 0.f;

    for (int k0 = 0; k0 < D_; k0 += 32) {
#pragma unroll
        for (int i = threadIdx.x; i < 64 * 32; i += 256) {
            int m = i >> 5, kk = i & 31;
            xs[m][kk] = X[(size_t)(rowBase + m) * D_ + k0 + kk];
            ws[m][kk] = W[(size_t)(colBase + m) * D_ + k0 + kk];
        }
        __syncthreads();
#pragma unroll
        for (int kk = 0; kk < 32; kk++) {
            float xv[4], wv[4];
#pragma unroll
            for (int i = 0; i < 4; i++) xv[i] = xs[ty * 4 + i][kk];
#pragma unroll
            for (int j = 0; j < 4; j++) wv[j] = ws[tx * 4 + j][kk];
#pragma unroll
            for (int i = 0; i < 4; i++)
#pragma unroll
                for (int j = 0; j < 4; j++) acc[i][j] += xv[i] * wv[j];
        }
        __syncthreads();
    }

#pragma unroll
    for (int i = 0; i < 4; i++) {
        int row = rowBase + ty * 4 + i;
#pragma unroll
        for (int j = 0; j < 4; j++) {
            int col = colBase + tx * 4 + j;
            float v = acc[i][j] + bias[col];
            if (mode == 0) {
                int b = row >> 11;
                int l = row & (L_ - 1);
                int head = col >> 5;
                int e = col & 31;
                Out[((size_t)((b * H_ + head) * L_ + l)) * h_ + e] = v;
            } else {
                Out[(size_t)row * D_ + col] = v;
            }
        }
    }
}

// =====================================================================
// K2 (fused): per-position sim/normalize/gate + per-chunk partials.
// grid = BH*NC = 512 blocks, 256 threads (8 warps), 8 positions/warp.
// =====================================================================
__global__ void chunk_fused_kernel(const float* __restrict__ kv_scale,
                                   const float* __restrict__ qk_scale,
                                   const float* __restrict__ wg_w,
                                   const float* __restrict__ wg_b) {
    __shared__ float ks[C_][33];
    __shared__ float vs[C_][33];
    __shared__ float gsh[C_];
    __shared__ float simsh[C_];
    __shared__ float msh[h_ * 33];

    int c = blockIdx.x & (NC_ - 1);
    int bh = blockIdx.x >> 5;
    int head = bh & (H_ - 1);
    int base = bh * L_ + c * C_;
    int lane = threadIdx.x & 31;
    int w = threadIdx.x >> 5;

    // stage gate matrix M = wg_w ∘ kv_scale[head] into padded smem
    for (int i = threadIdx.x; i < h_ * h_; i += 256)
        msh[(i >> 5) * 33 + (i & 31)] =
            wg_w[i] * kv_scale[(size_t)head * (h_ * h_) + i];
    __syncthreads();

    float Mreg[32];
#pragma unroll
    for (int e = 0; e < 32; e++) Mreg[e] = msh[lane * 33 + e];

    float qksc = qk_scale[head];
    float gb = wg_b[0];

    // ---- pointwise stage: 8 positions per warp ----
#pragma unroll
    for (int j = 0; j < C_ / 8; j++) {
        int l = w * (C_ / 8) + j;
        size_t gidx = (size_t)(base + l) * h_ + lane;
        float q = g_Q[gidx];
        float k = g_K[gidx];
        float v = g_V[gidx];

        float sim = warpSum(q * k) * qksc;
        float kn = sqrtf(warpSum(k * k));
        k = k / fmaxf(kn, 1e-12f);
        float vn = sqrtf(warpSum(v * v));
        v = v / fmaxf(vn, 1e-12f);

        float inner = 0.f;
#pragma unroll
        for (int e = 0; e < 32; e++)
            inner = fmaf(Mreg[e], __shfl_sync(0xffffffffu, k, e), inner);
        float logit = warpSum(v * inner) + gb;
        float r = fmaxf(logit, 0.f);
        float g = r * r + EPS_;

        ks[l][lane] = k;
        vs[l][lane] = v;
        g_K[gidx] = k;
        g_V[gidx] = v;
        if (lane == 0) {
            gsh[l] = g;
            simsh[l] = sim;
            g_gate[base + l] = g;
            g_sim[base + l] = sim;
        }
    }
    __syncthreads();

    // ---- Sdelta[d][e] = sum_i g_i * v[i][d] * k[i][e]; warp w: e=lane, d=w+8j
    float acc[4] = {0.f, 0.f, 0.f, 0.f};
    for (int i = 0; i < C_; i++) {
        float gk = gsh[i] * ks[i][lane];
#pragma unroll
        for (int j = 0; j < 4; j++) acc[j] += vs[i][w + 8 * j] * gk;
    }
    size_t sbase = (size_t)(bh * NC_ + c) * (h_ * h_);
#pragma unroll
    for (int j = 0; j < 4; j++) {
        int d = w + 8 * j;
        float sc = kv_scale[(size_t)head * (h_ * h_) + d * 32 + lane];
        g_Sdelta[sbase + d * 32 + lane] = acc[j] * sc;
    }

    // ---- scalar reductions (warp 0) ----
    if (threadIdx.x < 32) {
        float lm = -INFINITY, lg = 0.f;
#pragma unroll
        for (int j = 0; j < C_ / 32; j++) {
            lm = fmaxf(lm, simsh[lane + 32 * j]);
            lg += gsh[lane + 32 * j];
        }
        float mloc = warpMax(lm);
        float ls = 0.f;
#pragma unroll
        for (int j = 0; j < C_ / 32; j++) ls += expf(simsh[lane + 32 * j] - mloc);
        float sloc = warpSum(ls);
        float gsum = warpSum(lg);
        if (lane == 0) {
            int id = bh * NC_ + c;
            g_mloc[id] = mloc;
            g_sloc[id] = sloc;
            g_gsum[id] = gsum;
        }
    }
}

// =====================================================================
// K4: sequential exclusive scan over chunks. grid = BH = 16 blocks.
// =====================================================================
__global__ void chunk_scan_kernel() {
    int bh = blockIdx.x;
    int t = threadIdx.x;  // 256
    float acc[4] = {0.f, 0.f, 0.f, 0.f};
    for (int c = 0; c < NC_; c++) {
        size_t idx = (size_t)(bh * NC_ + c) * (h_ * h_);
#pragma unroll
        for (int j = 0; j < 4; j++) {
            g_Sprefix[idx + t + 256 * j] = acc[j];
            acc[j] += g_Sdelta[idx + t + 256 * j];
        }
    }
    if (t == 0) {
        float m = -INFINITY, s = 0.f, g = 0.f;
        for (int c = 0; c < NC_; c++) {
            int id = bh * NC_ + c;
            g_mpre[id] = m;
            g_spre[id] = s;
            g_gpre[id] = g;
            float mc = g_mloc[id], sc = g_sloc[id];
            float mn = fmaxf(m, mc);
            s = s * expf(m - mn) + sc * expf(mc - mn);
            m = mn;
            g += g_gsum[id];
        }
    }
}

// =====================================================================
// K5: chunk output. grid = BH*NC = 512 blocks, 256 threads.
// 4 threads per row l (8 output cols each), float4 smem access.
// =====================================================================
__global__ __launch_bounds__(256)
void chunk_output_kernel() {
    __shared__ float qs[C_ * P36];
    __shared__ float ksm[C_ * P36];
    __shared__ float vsm[C_ * P36];
    __shared__ float S0[h_ * P36];
    __shared__ float gsh[C_];
    __shared__ float simsh[C_];
    __shared__ float gcum[C_];
    __shared__ float msm[C_];
    __shared__ float ssm[C_];

    int c = blockIdx.x & (NC_ - 1);
    int bh = blockIdx.x >> 5;
    int head = bh & (H_ - 1);
    int b = bh >> 3;
    int base = bh * L_ + c * C_;
    int t = threadIdx.x;

    for (int i = t; i < C_ * h_; i += 256) {
        int l = i >> 5, d = i & 31;
        qs[l * P36 + d] = g_Q[(size_t)(base + l) * h_ + d];
        ksm[l * P36 + d] = g_K[(size_t)(base + l) * h_ + d];
        vsm[l * P36 + d] = g_V[(size_t)(base + l) * h_ + d];
    }
    size_t sbase = (size_t)(bh * NC_ + c) * (h_ * h_);
    for (int i = t; i < h_ * h_; i += 256) {
        int d = i >> 5, e = i & 31;
        S0[d * P36 + e] = g_Sprefix[sbase + i];
    }
    for (int i = t; i < C_; i += 256) {
        float gv = g_gate[base + i];
        float sv = g_sim[base + i];
        gsh[i] = gv;
        simsh[i] = sv;
        gcum[i] = gv;
        msm[i] = sv;
        ssm[i] = 1.f;
    }
    __syncthreads();

    // Hillis-Steele inclusive scans over C_=64 elements (threads 0..63)
    for (int off = 1; off < C_; off <<= 1) {
        float ga = 0.f, m2 = 0.f, s2 = 0.f;
        bool rd = (t < C_) && (t >= off);
        if (rd) {
            ga = gcum[t - off];
            m2 = msm[t - off];
            s2 = ssm[t - off];
        }
        __syncthreads();
        if (rd) {
            gcum[t] += ga;
            float m1 = msm[t], s1 = ssm[t];
            float mn = fmaxf(m1, m2);
            ssm[t] = s1 * expf(m1 - mn) + s2 * expf(m2 - mn);
            msm[t] = mn;
        }
        __syncthreads();
    }

    int id = bh * NC_ + c;
    float m0 = g_mpre[id], s0 = g_spre[id], g0 = g_gpre[id];

    // 4 threads per row l; each handles 8 output columns
    int l = t >> 2;
    int quad = t & 3;
    int eb = quad * 8;
    int lane = t & 31;
    unsigned gmask = 0xFu << (lane & ~3);

    // hoist full q row (for part A) and q slice (for part B)
    float qf[32];
#pragma unroll
    for (int m = 0; m < 8; m++) {
        float4 qv = *(const float4*)&qs[l * P36 + m * 4];
        qf[m * 4 + 0] = qv.x;
        qf[m * 4 + 1] = qv.y;
        qf[m * 4 + 2] = qv.z;
        qf[m * 4 + 3] = qv.w;
    }

    float acc[8];
#pragma unroll
    for (int j = 0; j < 8; j++) acc[j] = 0.f;

    // Part A: q_l @ S0 (cols eb..eb+7)
#pragma unroll 8
    for (int d = 0; d < 32; d++) {
        float4 sa = *(const float4*)&S0[d * P36 + eb];
        float4 sb = *(const float4*)&S0[d * P36 + eb + 4];
        float qv = qf[d];
        acc[0] = fmaf(qv, sa.x, acc[0]);
        acc[1] = fmaf(qv, sa.y, acc[1]);
        acc[2] = fmaf(qv, sa.z, acc[2]);
        acc[3] = fmaf(qv, sa.w, acc[3]);
        acc[4] = fmaf(qv, sb.x, acc[4]);
        acc[5] = fmaf(qv, sb.y, acc[5]);
        acc[6] = fmaf(qv, sb.z, acc[6]);
        acc[7] = fmaf(qv, sb.w, acc[7]);
    }

    // Part B: causal intra-chunk. Quad shares row l; dot split 8 dims each.
    float qe0 = qf[eb + 0], qe1 = qf[eb + 1], qe2 = qf[eb + 2], qe3 = qf[eb + 3];
    float qe4 = qf[eb + 4], qe5 = qf[eb + 5], qe6 = qf[eb + 6], qe7 = qf[eb + 7];
    for (int i = 0; i <= l; i++) {
        float4 va = *(const float4*)&vsm[i * P36 + eb];
        float4 vb = *(const float4*)&vsm[i * P36 + eb + 4];
        float p = qe0 * va.x + qe1 * va.y + qe2 * va.z + qe3 * va.w +
                  qe4 * vb.x + qe5 * vb.y + qe6 * vb.z + qe7 * vb.w;
        p += __shfl_xor_sync(gmask, p, 1);
        p += __shfl_xor_sync(gmask, p, 2);
        p *= gsh[i];
        float4 ka = *(const float4*)&ksm[i * P36 + eb];
        float4 kb = *(const float4*)&ksm[i * P36 + eb + 4];
        acc[0] = fmaf(p, ka.x, acc[0]);
        acc[1] = fmaf(p, ka.y, acc[1]);
        acc[2] = fmaf(p, ka.z, acc[2]);
        acc[3] = fmaf(p, ka.w, acc[3]);
        acc[4] = fmaf(p, kb.x, acc[4]);
        acc[5] = fmaf(p, kb.y, acc[5]);
        acc[6] = fmaf(p, kb.z, acc[6]);
        acc[7] = fmaf(p, kb.w, acc[7]);
    }

    // final scaling
    float ml = msm[l], sl = ssm[l];
    float mn = fmaxf(m0, ml);
    float sfull = s0 * expf(m0 - mn) + sl * expf(ml - mn);
    float w = expf(simsh[l] - mn) / (sfull + EPS_);
    float silu = w / (1.f + expf(-w));
    float gc = gcum[l] + g0;
    float factor = (1.f + silu) / (gc + EPS_);

    int lg = c * C_ + l;
    size_t obase = ((size_t)b * L_ + lg) * D_ + head * h_ + eb;
    float4 o0, o1;
    o0.x = acc[0] * factor;
    o0.y = acc[1] * factor;
    o0.z = acc[2] * factor;
    o0.w = acc[3] * factor;
    o1.x = acc[4] * factor;
    o1.y = acc[5] * factor;
    o1.z = acc[6] * factor;
    o1.w = acc[7] * factor;
    *(float4*)(g_ctxt + obase) = o0;
    *(float4*)(g_ctxt + obase + 4) = o1;
}

// =====================================================================
// launch
// =====================================================================
extern "C" void kernel_launch(void* const* d_in, const int* in_sizes, int n_in,
                              void* d_out, int out_size) {
    const float* x = (const float*)d_in[0];
    const float* wq_w = (const float*)d_in[1];
    const float* wq_b = (const float*)d_in[2];
    const float* wk_w = (const float*)d_in[3];
    const float* wk_b = (const float*)d_in[4];
    const float* wv_w = (const float*)d_in[5];
    const float* wv_b = (const float*)d_in[6];
    const float* wo_w = (const float*)d_in[7];
    const float* wo_b = (const float*)d_in[8];
    const float* wg_w = (const float*)d_in[9];
    const float* wg_b = (const float*)d_in[10];
    const float* kv_scale = (const float*)d_in[11];
    const float* qk_scale = (const float*)d_in[12];
    float* out = (float*)d_out;

    float* Qp; cudaGetSymbolAddress((void**)&Qp, g_Q);
    float* Kp; cudaGetSymbolAddress((void**)&Kp, g_K);
    float* Vp; cudaGetSymbolAddress((void**)&Vp, g_V);
    float* Cp; cudaGetSymbolAddress((void**)&Cp, g_ctxt);

    dim3 gg(B_ * L_ / 64, D_ / 64);

    gemm_bias_kernel<<<gg, 256>>>(x, wq_w, wq_b, Qp, 0);
    gemm_bias_kernel<<<gg, 256>>>(x, wk_w, wk_b, Kp, 0);
    gemm_bias_kernel<<<gg, 256>>>(x, wv_w, wv_b, Vp, 0);

    chunk_fused_kernel<<<BH_ * NC_, 256>>>(kv_scale, qk_scale, wg_w, wg_b);
    chunk_scan_kernel<<<BH_, 256>>>();
    chunk_output_kernel<<<BH_ * NC_, 256>>>();

    gemm_bias_kernel<<<gg, 256>>>(Cp, wo_w, wo_b, out, 1);
}

// round 9
// speedup vs baseline: 1.6975x; 1.4131x over previous
#include <cuda_runtime.h>
#include <cuda_bf16.h>
#include <mma.h>
#include <math.h>
#include <stdint.h>

using namespace nvcuda;

// Problem constants
#define B_  2
#define L_  2048
#define D_  256
#define H_  8
#define h_  32
#define C_  64            // chunk size
#define NC_ (L_ / C_)     // 32 chunks per (b,h)
#define BH_ (B_ * H_)     // 16
#define NPOS_ (BH_ * L_)  // 32768
#define EPS_ 1e-5f
#define P36 36            // float4-friendly smem pitch

// -------- scratch (device globals, no allocation) --------
__device__ float g_Q[NPOS_ * h_];      // [B,H,L,h]
__device__ float g_K[NPOS_ * h_];
__device__ float g_V[NPOS_ * h_];
__device__ float g_sim[NPOS_];
__device__ float g_gate[NPOS_];
__device__ float g_Sdelta[BH_ * NC_ * h_ * h_];
__device__ float g_Sprefix[BH_ * NC_ * h_ * h_];
__device__ float g_gsum[BH_ * NC_];
__device__ float g_mloc[BH_ * NC_];
__device__ float g_sloc[BH_ * NC_];
__device__ float g_gpre[BH_ * NC_];
__device__ float g_mpre[BH_ * NC_];
__device__ float g_spre[BH_ * NC_];
__device__ float g_ctxt[B_ * L_ * D_];  // [B,L,D]

// bf16 split buffers (hi + lo ~ fp32 via 3x bf16 MMA)
__device__ __align__(16) __nv_bfloat16 g_xhi[B_ * L_ * D_];
__device__ __align__(16) __nv_bfloat16 g_xlo[B_ * L_ * D_];
__device__ __align__(16) __nv_bfloat16 g_whi[4 * D_ * D_];   // q,k,v,o
__device__ __align__(16) __nv_bfloat16 g_wlo[4 * D_ * D_];
__device__ __align__(16) __nv_bfloat16 g_chi[B_ * L_ * D_];
__device__ __align__(16) __nv_bfloat16 g_clo[B_ * L_ * D_];

// -------- helpers --------
__device__ __forceinline__ float warpSum(float v) {
#pragma unroll
    for (int o = 16; o > 0; o >>= 1) v += __shfl_xor_sync(0xffffffffu, v, o);
    return v;
}
__device__ __forceinline__ float warpMax(float v) {
#pragma unroll
    for (int o = 16; o > 0; o >>= 1) v = fmaxf(v, __shfl_xor_sync(0xffffffffu, v, o));
    return v;
}

// =====================================================================
// convert: fp32 -> (bf16 hi, bf16 lo)
// =====================================================================
__global__ void convert_split_kernel(const float* __restrict__ src,
                                     __nv_bfloat16* __restrict__ hi,
                                     __nv_bfloat16* __restrict__ lo) {
    int i = blockIdx.x * 256 + threadIdx.x;
    float4 v = ((const float4*)src)[i];
    __nv_bfloat16 h0 = __float2bfloat16(v.x);
    __nv_bfloat16 h1 = __float2bfloat16(v.y);
    __nv_bfloat16 h2 = __float2bfloat16(v.z);
    __nv_bfloat16 h3 = __float2bfloat16(v.w);
    __nv_bfloat16 l0 = __float2bfloat16(v.x - __bfloat162float(h0));
    __nv_bfloat16 l1 = __float2bfloat16(v.y - __bfloat162float(h1));
    __nv_bfloat16 l2 = __float2bfloat16(v.z - __bfloat162float(h2));
    __nv_bfloat16 l3 = __float2bfloat16(v.w - __bfloat162float(h3));
    __nv_bfloat162* H = (__nv_bfloat162*)hi;
    __nv_bfloat162* Lo = (__nv_bfloat162*)lo;
    H[2 * i] = __nv_bfloat162(h0, h1);
    H[2 * i + 1] = __nv_bfloat162(h2, h3);
    Lo[2 * i] = __nv_bfloat162(l0, l1);
    Lo[2 * i + 1] = __nv_bfloat162(l2, l3);
}

// all 4 weight matrices in one launch: grid = 4*64 blocks
__global__ void convert_w_kernel(const float* __restrict__ w0,
                                 const float* __restrict__ w1,
                                 const float* __restrict__ w2,
                                 const float* __restrict__ w3) {
    int mat = blockIdx.x >> 6;
    int i = (blockIdx.x & 63) * 256 + threadIdx.x;  // float4 index
    const float* src = (mat == 0) ? w0 : (mat == 1) ? w1 : (mat == 2) ? w2 : w3;
    float4 v = ((const float4*)src)[i];
    __nv_bfloat16 h0 = __float2bfloat16(v.x);
    __nv_bfloat16 h1 = __float2bfloat16(v.y);
    __nv_bfloat16 h2 = __float2bfloat16(v.z);
    __nv_bfloat16 h3 = __float2bfloat16(v.w);
    __nv_bfloat16 l0 = __float2bfloat16(v.x - __bfloat162float(h0));
    __nv_bfloat16 l1 = __float2bfloat16(v.y - __bfloat162float(h1));
    __nv_bfloat16 l2 = __float2bfloat16(v.z - __bfloat162float(h2));
    __nv_bfloat16 l3 = __float2bfloat16(v.w - __bfloat162float(h3));
    size_t o2 = (size_t)mat * (D_ * D_ / 2) + 2 * (size_t)i;
    __nv_bfloat162* H = (__nv_bfloat162*)g_whi;
    __nv_bfloat162* Lo = (__nv_bfloat162*)g_wlo;
    H[o2] = __nv_bfloat162(h0, h1);
    H[o2 + 1] = __nv_bfloat162(h2, h3);
    Lo[o2] = __nv_bfloat162(l0, l1);
    Lo[o2 + 1] = __nv_bfloat162(l2, l3);
}

// =====================================================================
// WMMA split-bf16 GEMM. Out[n,o] = sum_i X[n,i]*W[o,i] + bias[o]
// Block tile 128x64, 8 warps (4x2), warp tile 32x32 (2x2 wmma frags),
// K slab 32 in smem, 3 MMAs per fragment pair (hihi + hilo + lohi).
// mode 0: col space [q|k|v] (N=768), scatter to [B,H,L,h].
// mode 1: row-major 256-wide into Out0.
// =====================================================================
#define TM_ 128
#define TN_ 64
#define KSL 32
#define XP 40   // bf16 smem pitch (80B rows, 16B aligned)
#define CP 72   // float epilogue pitch

__global__ __launch_bounds__(256)
void mma_gemm_kernel(const __nv_bfloat16* __restrict__ Ahi,
                     const __nv_bfloat16* __restrict__ Alo,
                     const float* __restrict__ bias0,
                     const float* __restrict__ bias1,
                     const float* __restrict__ bias2,
                     float* __restrict__ Out0,
                     float* __restrict__ Out1,
                     float* __restrict__ Out2,
                     int wbase, int mode) {
    __shared__ __align__(16) union {
        struct {
            __nv_bfloat16 xh[TM_ * XP];
            __nv_bfloat16 xl[TM_ * XP];
            __nv_bfloat16 wh[TN_ * XP];
            __nv_bfloat16 wl[TN_ * XP];
        } s;
        float cbuf[TM_ * CP];
    } u;

    const int tid = threadIdx.x;
    const int wid = tid >> 5;
    const int wm = wid & 3;          // 4 warps along M
    const int wn = wid >> 2;         // 2 warps along N
    const int rowBase = blockIdx.x * TM_;
    const int gc0 = blockIdx.y * TN_;
    const int mat = gc0 >> 8;
    const int colLoc = gc0 & 255;

    const __nv_bfloat16* Whi =
        g_whi + (size_t)(wbase + mat) * (D_ * D_) + (size_t)colLoc * D_;
    const __nv_bfloat16* Wlo =
        g_wlo + (size_t)(wbase + mat) * (D_ * D_) + (size_t)colLoc * D_;

    wmma::fragment<wmma::accumulator, 16, 16, 16, float> c[2][2];
#pragma unroll
    for (int i = 0; i < 2; i++)
#pragma unroll
        for (int j = 0; j < 2; j++) wmma::fill_fragment(c[i][j], 0.f);

    for (int s = 0; s < D_ / KSL; s++) {
        // stage X (128x32 hi+lo) and W (64x32 hi+lo) into smem, uint4 = 8 bf16
        {
            const __nv_bfloat16* Ah = Ahi + (size_t)rowBase * D_ + s * KSL;
            const __nv_bfloat16* Al = Alo + (size_t)rowBase * D_ + s * KSL;
#pragma unroll
            for (int t = 0; t < 2; t++) {
                int i = tid + t * 256;      // 512 uint4 loads for 128x32
                int r = i >> 2, cg = (i & 3) * 8;
                *(uint4*)&u.s.xh[r * XP + cg] = *(const uint4*)(Ah + (size_t)r * D_ + cg);
                *(uint4*)&u.s.xl[r * XP + cg] = *(const uint4*)(Al + (size_t)r * D_ + cg);
            }
            const __nv_bfloat16* Bh = Whi + s * KSL;
            const __nv_bfloat16* Bl = Wlo + s * KSL;
            int r = tid >> 2, cg = (tid & 3) * 8;  // 256 uint4 loads for 64x32
            *(uint4*)&u.s.wh[r * XP + cg] = *(const uint4*)(Bh + (size_t)r * D_ + cg);
            *(uint4*)&u.s.wl[r * XP + cg] = *(const uint4*)(Bl + (size_t)r * D_ + cg);
        }
        __syncthreads();

#pragma unroll
        for (int kk = 0; kk < KSL; kk += 16) {
            wmma::fragment<wmma::matrix_a, 16, 16, 16, __nv_bfloat16, wmma::row_major> ah[2], al[2];
            wmma::fragment<wmma::matrix_b, 16, 16, 16, __nv_bfloat16, wmma::col_major> bh[2], bl[2];
#pragma unroll
            for (int i = 0; i < 2; i++) {
                const __nv_bfloat16* pa = &u.s.xh[(wm * 32 + i * 16) * XP + kk];
                const __nv_bfloat16* pl = &u.s.xl[(wm * 32 + i * 16) * XP + kk];
                wmma::load_matrix_sync(ah[i], pa, XP);
                wmma::load_matrix_sync(al[i], pl, XP);
            }
#pragma unroll
            for (int j = 0; j < 2; j++) {
                const __nv_bfloat16* pb = &u.s.wh[(wn * 32 + j * 16) * XP + kk];
                const __nv_bfloat16* pl = &u.s.wl[(wn * 32 + j * 16) * XP + kk];
                wmma::load_matrix_sync(bh[j], pb, XP);
                wmma::load_matrix_sync(bl[j], pl, XP);
            }
#pragma unroll
            for (int i = 0; i < 2; i++)
#pragma unroll
                for (int j = 0; j < 2; j++) {
                    wmma::mma_sync(c[i][j], ah[i], bh[j], c[i][j]);
                    wmma::mma_sync(c[i][j], ah[i], bl[j], c[i][j]);
                    wmma::mma_sync(c[i][j], al[i], bh[j], c[i][j]);
                }
        }
        __syncthreads();
    }

    // epilogue: frags -> smem float buffer
#pragma unroll
    for (int i = 0; i < 2; i++)
#pragma unroll
        for (int j = 0; j < 2; j++)
            wmma::store_matrix_sync(&u.cbuf[(wm * 32 + i * 16) * CP + wn * 32 + j * 16],
                                    c[i][j], CP, wmma::mem_row_major);
    __syncthreads();

    const float* Bv = (mat == 0) ? bias0 : (mat == 1) ? bias1 : bias2;
    float* Out = (mat == 0) ? Out0 : (mat == 1) ? Out1 : Out2;

    // scatter: 128x64 floats = 2048 float4, 8 per thread
#pragma unroll
    for (int t = 0; t < 8; t++) {
        int f = tid + t * 256;
        int r = f >> 4;            // row within tile
        int col = (f & 15) * 4;    // col within tile (4-aligned)
        float4 o;
        o.x = u.cbuf[r * CP + col + 0] + Bv[colLoc + col + 0];
        o.y = u.cbuf[r * CP + col + 1] + Bv[colLoc + col + 1];
        o.z = u.cbuf[r * CP + col + 2] + Bv[colLoc + col + 2];
        o.w = u.cbuf[r * CP + col + 3] + Bv[colLoc + col + 3];
        int row = rowBase + r;
        if (mode == 0) {
            int b = row >> 11;
            int l = row & (L_ - 1);
            int gcol = gc0 + col;
            int head = (gcol >> 5) & 7;
            int e = gcol & 31;
            size_t ob = ((size_t)((b * H_ + head) * L_ + l)) * h_ + e;
            *(float4*)(Out + ob) = o;
        } else {
            *(float4*)(Out0 + (size_t)row * D_ + gc0 + col) = o;
        }
    }
}

// =====================================================================
// K2 (fused): per-position sim/normalize/gate + per-chunk partials.
// grid = BH*NC = 512 blocks, 256 threads (8 warps), 8 positions/warp.
// =====================================================================
__global__ void chunk_fused_kernel(const float* __restrict__ kv_scale,
                                   const float* __restrict__ qk_scale,
                                   const float* __restrict__ wg_w,
                                   const float* __restrict__ wg_b) {
    __shared__ float ks[C_][33];
    __shared__ float vs[C_][33];
    __shared__ float gsh[C_];
    __shared__ float simsh[C_];
    __shared__ float msh[h_ * 33];

    int c = blockIdx.x & (NC_ - 1);
    int bh = blockIdx.x >> 5;
    int head = bh & (H_ - 1);
    int base = bh * L_ + c * C_;
    int lane = threadIdx.x & 31;
    int w = threadIdx.x >> 5;

    for (int i = threadIdx.x; i < h_ * h_; i += 256)
        msh[(i >> 5) * 33 + (i & 31)] =
            wg_w[i] * kv_scale[(size_t)head * (h_ * h_) + i];
    __syncthreads();

    float Mreg[32];
#pragma unroll
    for (int e = 0; e < 32; e++) Mreg[e] = msh[lane * 33 + e];

    float qksc = qk_scale[head];
    float gb = wg_b[0];

#pragma unroll
    for (int j = 0; j < C_ / 8; j++) {
        int l = w * (C_ / 8) + j;
        size_t gidx = (size_t)(base + l) * h_ + lane;
        float q = g_Q[gidx];
        float k = g_K[gidx];
        float v = g_V[gidx];

        float sim = warpSum(q * k) * qksc;
        float kn = sqrtf(warpSum(k * k));
        k = k / fmaxf(kn, 1e-12f);
        float vn = sqrtf(warpSum(v * v));
        v = v / fmaxf(vn, 1e-12f);

        float inner = 0.f;
#pragma unroll
        for (int e = 0; e < 32; e++)
            inner = fmaf(Mreg[e], __shfl_sync(0xffffffffu, k, e), inner);
        float logit = warpSum(v * inner) + gb;
        float r = fmaxf(logit, 0.f);
        float g = r * r + EPS_;

        ks[l][lane] = k;
        vs[l][lane] = v;
        g_K[gidx] = k;
        g_V[gidx] = v;
        if (lane == 0) {
            gsh[l] = g;
            simsh[l] = sim;
            g_gate[base + l] = g;
            g_sim[base + l] = sim;
        }
    }
    __syncthreads();

    float acc[4] = {0.f, 0.f, 0.f, 0.f};
    for (int i = 0; i < C_; i++) {
        float gk = gsh[i] * ks[i][lane];
#pragma unroll
        for (int j = 0; j < 4; j++) acc[j] += vs[i][w + 8 * j] * gk;
    }
    size_t sbase = (size_t)(bh * NC_ + c) * (h_ * h_);
#pragma unroll
    for (int j = 0; j < 4; j++) {
        int d = w + 8 * j;
        float sc = kv_scale[(size_t)head * (h_ * h_) + d * 32 + lane];
        g_Sdelta[sbase + d * 32 + lane] = acc[j] * sc;
    }

    if (threadIdx.x < 32) {
        float lm = -INFINITY, lg = 0.f;
#pragma unroll
        for (int j = 0; j < C_ / 32; j++) {
            lm = fmaxf(lm, simsh[lane + 32 * j]);
            lg += gsh[lane + 32 * j];
        }
        float mloc = warpMax(lm);
        float ls = 0.f;
#pragma unroll
        for (int j = 0; j < C_ / 32; j++) ls += expf(simsh[lane + 32 * j] - mloc);
        float sloc = warpSum(ls);
        float gsum = warpSum(lg);
        if (lane == 0) {
            int id = bh * NC_ + c;
            g_mloc[id] = mloc;
            g_sloc[id] = sloc;
            g_gsum[id] = gsum;
        }
    }
}

// =====================================================================
// K4: sequential exclusive scan over chunks. grid = BH = 16 blocks.
// =====================================================================
__global__ void chunk_scan_kernel() {
    int bh = blockIdx.x;
    int t = threadIdx.x;  // 256
    float acc[4] = {0.f, 0.f, 0.f, 0.f};
    for (int c = 0; c < NC_; c++) {
        size_t idx = (size_t)(bh * NC_ + c) * (h_ * h_);
#pragma unroll
        for (int j = 0; j < 4; j++) {
            g_Sprefix[idx + t + 256 * j] = acc[j];
            acc[j] += g_Sdelta[idx + t + 256 * j];
        }
    }
    if (t == 0) {
        float m = -INFINITY, s = 0.f, g = 0.f;
        for (int c = 0; c < NC_; c++) {
            int id = bh * NC_ + c;
            g_mpre[id] = m;
            g_spre[id] = s;
            g_gpre[id] = g;
            float mc = g_mloc[id], sc = g_sloc[id];
            float mn = fmaxf(m, mc);
            s = s * expf(m - mn) + sc * expf(mc - mn);
            m = mn;
            g += g_gsum[id];
        }
    }
}

// =====================================================================
// K5: chunk output. grid = BH*NC = 512 blocks, 256 threads.
// 4 threads per row l (8 output cols each), float4 smem access.
// =====================================================================
__global__ __launch_bounds__(256)
void chunk_output_kernel() {
    __shared__ float qs[C_ * P36];
    __shared__ float ksm[C_ * P36];
    __shared__ float vsm[C_ * P36];
    __shared__ float S0[h_ * P36];
    __shared__ float gsh[C_];
    __shared__ float simsh[C_];
    __shared__ float gcum[C_];
    __shared__ float msm[C_];
    __shared__ float ssm[C_];

    int c = blockIdx.x & (NC_ - 1);
    int bh = blockIdx.x >> 5;
    int head = bh & (H_ - 1);
    int b = bh >> 3;
    int base = bh * L_ + c * C_;
    int t = threadIdx.x;

    for (int i = t; i < C_ * h_; i += 256) {
        int l = i >> 5, d = i & 31;
        qs[l * P36 + d] = g_Q[(size_t)(base + l) * h_ + d];
        ksm[l * P36 + d] = g_K[(size_t)(base + l) * h_ + d];
        vsm[l * P36 + d] = g_V[(size_t)(base + l) * h_ + d];
    }
    size_t sbase = (size_t)(bh * NC_ + c) * (h_ * h_);
    for (int i = t; i < h_ * h_; i += 256) {
        int d = i >> 5, e = i & 31;
        S0[d * P36 + e] = g_Sprefix[sbase + i];
    }
    for (int i = t; i < C_; i += 256) {
        float gv = g_gate[base + i];
        float sv = g_sim[base + i];
        gsh[i] = gv;
        simsh[i] = sv;
        gcum[i] = gv;
        msm[i] = sv;
        ssm[i] = 1.f;
    }
    __syncthreads();

    for (int off = 1; off < C_; off <<= 1) {
        float ga = 0.f, m2 = 0.f, s2 = 0.f;
        bool rd = (t < C_) && (t >= off);
        if (rd) {
            ga = gcum[t - off];
            m2 = msm[t - off];
            s2 = ssm[t - off];
        }
        __syncthreads();
        if (rd) {
            gcum[t] += ga;
            float m1 = msm[t], s1 = ssm[t];
            float mn = fmaxf(m1, m2);
            ssm[t] = s1 * expf(m1 - mn) + s2 * expf(m2 - mn);
            msm[t] = mn;
        }
        __syncthreads();
    }

    int id = bh * NC_ + c;
    float m0 = g_mpre[id], s0 = g_spre[id], g0 = g_gpre[id];

    int l = t >> 2;
    int quad = t & 3;
    int eb = quad * 8;
    int lane = t & 31;
    unsigned gmask = 0xFu << (lane & ~3);

    float qf[32];
#pragma unroll
    for (int m = 0; m < 8; m++) {
        float4 qv = *(const float4*)&qs[l * P36 + m * 4];
        qf[m * 4 + 0] = qv.x;
        qf[m * 4 + 1] = qv.y;
        qf[m * 4 + 2] = qv.z;
        qf[m * 4 + 3] = qv.w;
    }

    float acc[8];
#pragma unroll
    for (int j = 0; j < 8; j++) acc[j] = 0.f;

#pragma unroll 8
    for (int d = 0; d < 32; d++) {
        float4 sa = *(const float4*)&S0[d * P36 + eb];
        float4 sb = *(const float4*)&S0[d * P36 + eb + 4];
        float qv = qf[d];
        acc[0] = fmaf(qv, sa.x, acc[0]);
        acc[1] = fmaf(qv, sa.y, acc[1]);
        acc[2] = fmaf(qv, sa.z, acc[2]);
        acc[3] = fmaf(qv, sa.w, acc[3]);
        acc[4] = fmaf(qv, sb.x, acc[4]);
        acc[5] = fmaf(qv, sb.y, acc[5]);
        acc[6] = fmaf(qv, sb.z, acc[6]);
        acc[7] = fmaf(qv, sb.w, acc[7]);
    }

    float qe0 = qf[eb + 0], qe1 = qf[eb + 1], qe2 = qf[eb + 2], qe3 = qf[eb + 3];
    float qe4 = qf[eb + 4], qe5 = qf[eb + 5], qe6 = qf[eb + 6], qe7 = qf[eb + 7];
    for (int i = 0; i <= l; i++) {
        float4 va = *(const float4*)&vsm[i * P36 + eb];
        float4 vb = *(const float4*)&vsm[i * P36 + eb + 4];
        float p = qe0 * va.x + qe1 * va.y + qe2 * va.z + qe3 * va.w +
                  qe4 * vb.x + qe5 * vb.y + qe6 * vb.z + qe7 * vb.w;
        p += __shfl_xor_sync(gmask, p, 1);
        p += __shfl_xor_sync(gmask, p, 2);
        p *= gsh[i];
        float4 ka = *(const float4*)&ksm[i * P36 + eb];
        float4 kb = *(const float4*)&ksm[i * P36 + eb + 4];
        acc[0] = fmaf(p, ka.x, acc[0]);
        acc[1] = fmaf(p, ka.y, acc[1]);
        acc[2] = fmaf(p, ka.z, acc[2]);
        acc[3] = fmaf(p, ka.w, acc[3]);
        acc[4] = fmaf(p, kb.x, acc[4]);
        acc[5] = fmaf(p, kb.y, acc[5]);
        acc[6] = fmaf(p, kb.z, acc[6]);
        acc[7] = fmaf(p, kb.w, acc[7]);
    }

    float ml = msm[l], sl = ssm[l];
    float mn = fmaxf(m0, ml);
    float sfull = s0 * expf(m0 - mn) + sl * expf(ml - mn);
    float w = expf(simsh[l] - mn) / (sfull + EPS_);
    float silu = w / (1.f + expf(-w));
    float gc = gcum[l] + g0;
    float factor = (1.f + silu) / (gc + EPS_);

    int lg = c * C_ + l;
    size_t obase = ((size_t)b * L_ + lg) * D_ + head * h_ + eb;
    float4 o0, o1;
    o0.x = acc[0] * factor;
    o0.y = acc[1] * factor;
    o0.z = acc[2] * factor;
    o0.w = acc[3] * factor;
    o1.x = acc[4] * factor;
    o1.y = acc[5] * factor;
    o1.z = acc[6] * factor;
    o1.w = acc[7] * factor;
    *(float4*)(g_ctxt + obase) = o0;
    *(float4*)(g_ctxt + obase + 4) = o1;
}

// =====================================================================
// launch
// =====================================================================
extern "C" void kernel_launch(void* const* d_in, const int* in_sizes, int n_in,
                              void* d_out, int out_size) {
    const float* x = (const float*)d_in[0];
    const float* wq_w = (const float*)d_in[1];
    const float* wq_b = (const float*)d_in[2];
    const float* wk_w = (const float*)d_in[3];
    const float* wk_b = (const float*)d_in[4];
    const float* wv_w = (const float*)d_in[5];
    const float* wv_b = (const float*)d_in[6];
    const float* wo_w = (const float*)d_in[7];
    const float* wo_b = (const float*)d_in[8];
    const float* wg_w = (const float*)d_in[9];
    const float* wg_b = (const float*)d_in[10];
    const float* kv_scale = (const float*)d_in[11];
    const float* qk_scale = (const float*)d_in[12];
    float* out = (float*)d_out;

    float* Qp; cudaGetSymbolAddress((void**)&Qp, g_Q);
    float* Kp; cudaGetSymbolAddress((void**)&Kp, g_K);
    float* Vp; cudaGetSymbolAddress((void**)&Vp, g_V);
    float* Cp; cudaGetSymbolAddress((void**)&Cp, g_ctxt);
    __nv_bfloat16* xhi; cudaGetSymbolAddress((void**)&xhi, g_xhi);
    __nv_bfloat16* xlo; cudaGetSymbolAddress((void**)&xlo, g_xlo);
    __nv_bfloat16* chi; cudaGetSymbolAddress((void**)&chi, g_chi);
    __nv_bfloat16* clo; cudaGetSymbolAddress((void**)&clo, g_clo);

    // converts
    convert_split_kernel<<<(B_ * L_ * D_) / 4 / 256, 256>>>(x, xhi, xlo);
    convert_w_kernel<<<4 * 64, 256>>>(wq_w, wk_w, wv_w, wo_w);

    // fused QKV projection on tensor cores (WMMA bf16 split)
    dim3 gqkv(B_ * L_ / TM_, 3 * D_ / TN_);
    mma_gemm_kernel<<<gqkv, 256>>>(xhi, xlo, wq_b, wk_b, wv_b,
                                   Qp, Kp, Vp, 0, 0);

    chunk_fused_kernel<<<BH_ * NC_, 256>>>(kv_scale, qk_scale, wg_w, wg_b);
    chunk_scan_kernel<<<BH_, 256>>>();
    chunk_output_kernel<<<BH_ * NC_, 256>>>();

    // output projection
    convert_split_kernel<<<(B_ * L_ * D_) / 4 / 256, 256>>>(Cp, chi, clo);
    dim3 gout(B_ * L_ / TM_, D_ / TN_);
    mma_gemm_kernel<<<gout, 256>>>(chi, clo, wo_b, wo_b, wo_b,
                                   out, out, out, 3, 1);
}